// round 12
// baseline (speedup 1.0000x reference)
#include <cuda_runtime.h>
#include <cstdint>

// ---------------------------------------------------------------------------
// Sequential LSTM rollout, N=10000 steps, H=1024.
// 128 persistent CTAs x 256 threads, W_hh in registers (f32x2 pairs).
// R12: flag+data colocated in per-CTA 128B chunks {8 x float h, flag}.
//   Publish (R1/R7-proven chain, per-CTA, no atomics):
//     lanes<8 st.cg h -> __syncwarp -> lane0 __threadfence -> st.release flag
//   Observe (per-warp): lanes 0-15 ld.acquire the 16 producer flags of this
//     warp's k-slice (CTAs 16w..16w+15), lane16 the OWN-CTA flag (bounds
//     run-ahead to 1 step), exit via __all_sync; then each lane<16 __ldcg's
//     its chunk's 8 floats into warp-private smem.
//   Contention: flags spread over 128 distinct 128B lines -> ~136 pollers
//   per line (same per-line load as R7's proven single counter).
// Reduce path identical to R7: parity-double-buffered sh_part, ONE
// __syncthreads per step, warp0 reduce + parallel activations + publish.
// Safety: all 8 warps of every CTA jointly poll all 128 producers =>
// publishing t+1 implies that CTA finished reading h_t => 1-step skew bound
// => parity buffers overwrite-safe (same induction as R7).
// CTA b owns h[8b..8b+8) and gate rows {g*1024 + 8b + j}.
// Warp w owns k in [128w,128w+128).
// ---------------------------------------------------------------------------

#define HDIM  1024
#define NCTA  128
#define TPB   256
#define NWARP 8
#define WPT   64           // f32x2 weight pairs per thread (=128 k floats)

typedef unsigned long long ull;

struct __align__(128) Chunk {
    float    h[8];         // 32B: this CTA's h values
    unsigned flag;         // step id (t+1 after step t), strong release/acquire
    unsigned pad[23];      // pad to 128B: one L2 line per chunk
};

__device__ Chunk g_chunk[2][NCTA];   // double-buffered by step parity

__device__ __forceinline__ ull ffma2(ull a, ull b, ull c) {
    ull d;
    asm("fma.rn.f32x2 %0, %1, %2, %3;" : "=l"(d) : "l"(a), "l"(b), "l"(c));
    return d;
}
__device__ __forceinline__ ull fadd2(ull a, ull b) {
    ull d;
    asm("add.rn.f32x2 %0, %1, %2;" : "=l"(d) : "l"(a), "l"(b));
    return d;
}
__device__ __forceinline__ float pairsum(ull a) {
    float lo = __uint_as_float((unsigned)(a & 0xffffffffull));
    float hi = __uint_as_float((unsigned)(a >> 32));
    return lo + hi;
}
__device__ __forceinline__ float sigf(float x) {
    return 1.0f / (1.0f + __expf(-x));
}
__device__ __forceinline__ unsigned ld_acq_gpu(const unsigned* p) {
    unsigned v;
    asm volatile("ld.acquire.gpu.u32 %0, [%1];" : "=r"(v) : "l"(p));
    return v;
}

__global__ void lstm_init_kernel() {
    int i = threadIdx.x;
    if (i < NCTA) { g_chunk[0][i].flag = 0u; g_chunk[1][i].flag = 0u; }
}

__global__ void __launch_bounds__(TPB) lstm_kernel(
    const float* __restrict__ x,      // [1024]
    const float* __restrict__ W_ih,   // [4096,1024] row-major
    const float* __restrict__ W_hh,   // [4096,1024] row-major
    const float* __restrict__ b_ih,   // [4096]
    const float* __restrict__ b_hh,   // [4096]
    float* __restrict__ out,          // [N,1024]
    int N)
{
    __shared__ float sh_h[HDIM];           // warp w owns [128w,128w+128): private
    __shared__ float sh_part[2][TPB];      // parity-double-buffered partials

    const int tid = threadIdx.x;
    const int w   = tid >> 5;
    const int l   = tid & 31;
    const int cta = blockIdx.x;
    const int gt  = l >> 3;                // gate 0..3 (i,f,g,o)
    const int jj  = l & 7;                 // local h index 0..7
    const int rowG = gt * HDIM + cta * 8 + jj;

    // poll mapping: lanes 0-15 -> producer CTAs of this warp's slice,
    // lane 16 -> own CTA (run-ahead bound), others inactive
    const int  pollIdx = (l < 16) ? (w * 16 + l) : cta;
    const bool doPoll  = (l <= 16);

    // ---- stage x into shared (reuse sh_h) ----
    ((float4*)sh_h)[tid] = ((const float4*)x)[tid];
    __syncthreads();

    // ---- prologue: x_gates = x @ W_ih^T + b_ih + b_hh for this CTA's rows ----
    float xg = 0.f;
    {
        const ull* wp = (const ull*)W_ih + (size_t)rowG * (HDIM / 2) + w * WPT;
        const ull* hp = (const ull*)sh_h + w * WPT;
        ull a0 = 0, a1 = 0, a2 = 0, a3 = 0;
        #pragma unroll
        for (int i = 0; i < WPT; i += 4) {
            a0 = ffma2(wp[i + 0], hp[i + 0], a0);
            a1 = ffma2(wp[i + 1], hp[i + 1], a1);
            a2 = ffma2(wp[i + 2], hp[i + 2], a2);
            a3 = ffma2(wp[i + 3], hp[i + 3], a3);
        }
        a0 = fadd2(a0, a1); a2 = fadd2(a2, a3); a0 = fadd2(a0, a2);
        sh_part[0][w * 32 + l] = pairsum(a0);
        __syncthreads();
        if (w == 0) {
            float s = 0.f;
            #pragma unroll
            for (int ww = 0; ww < NWARP; ww++) s += sh_part[0][ww * 32 + l];
            xg = s + b_ih[rowG] + b_hh[rowG];
        }
        __syncthreads();
    }

    // ---- preload W_hh slice into registers ----
    ull wreg[WPT];
    {
        const ull* wp = (const ull*)W_hh + (size_t)rowG * (HDIM / 2) + w * WPT;
        #pragma unroll
        for (int i = 0; i < WPT; i++) wreg[i] = wp[i];
    }

    // ---- recurrence: ONE __syncthreads per step ----
    float c = 0.f;

    for (int t = 0; t < N; ++t) {
        float dot = 0.f;
        if (t > 0) {
            const int p = (t - 1) & 1;
            const unsigned tt = (unsigned)t;
            const Chunk* ch = &g_chunk[p][pollIdx];

            // per-warp acquire poll: 16 producer flags + own flag
            bool ok;
            do {
                ok = doPoll ? ((int)(ld_acq_gpu(&ch->flag) - tt) >= 0) : true;
            } while (!__all_sync(0xffffffffu, ok));

            // lanes 0-15: fetch this chunk's 8 floats into warp-private smem
            if (l < 16) {
                float4 d0 = __ldcg((const float4*)ch->h);
                float4 d1 = __ldcg((const float4*)ch->h + 1);
                *((float4*)(sh_h + w * 128 + l * 8))     = d0;
                *((float4*)(sh_h + w * 128 + l * 8 + 4)) = d1;
            }
            __syncwarp();

            const ull* hp = (const ull*)(sh_h + w * 128);
            ull c0 = 0, c1 = 0, c2 = 0, c3 = 0;
            #pragma unroll
            for (int i = 0; i < WPT; i += 4) {
                c0 = ffma2(wreg[i + 0], hp[i + 0], c0);
                c1 = ffma2(wreg[i + 1], hp[i + 1], c1);
                c2 = ffma2(wreg[i + 2], hp[i + 2], c2);
                c3 = ffma2(wreg[i + 3], hp[i + 3], c3);
            }
            c0 = fadd2(c0, c1); c2 = fadd2(c2, c3); c0 = fadd2(c0, c2);
            dot = pairsum(c0);
        }
        sh_part[t & 1][w * 32 + l] = dot;
        __syncthreads();

        if (w == 0) {
            float s = 0.f;
            #pragma unroll
            for (int ww = 0; ww < NWARP; ww++) s += sh_part[t & 1][ww * 32 + l];
            // activation on ALL 32 lanes (parallel MUFU), then gather
            float val = xg + s;
            float act = (gt == 2) ? tanhf(val) : sigf(val);
            float a_f = __shfl_sync(0xffffffffu, act, l + 8);
            float a_g = __shfl_sync(0xffffffffu, act, l + 16);
            float a_o = __shfl_sync(0xffffffffu, act, l + 24);
            float hn = 0.f;
            if (l < 8) {
                c  = a_f * c + act * a_g;       // act=i, a_f=f, a_g=g
                hn = a_o * tanhf(c);
                __stcg(&g_chunk[t & 1][cta].h[l], hn);
            }
            __syncwarp();
            if (l == 0) {
                __threadfence();
                asm volatile("st.release.gpu.u32 [%0], %1;"
                             :: "l"(&g_chunk[t & 1][cta].flag),
                                "r"((unsigned)(t + 1))
                             : "memory");
            }
            // out store AFTER release: fence never drains the DRAM write
            if (l < 8)
                __stcs(out + (size_t)t * HDIM + cta * 8 + l, hn);
        }
        // no trailing barrier: sh_part for step t+1 has opposite parity; the
        // joint 8-warp poll covers all 128 producers, bounding skew to 1 step.
    }
}

extern "C" void kernel_launch(void* const* d_in, const int* in_sizes, int n_in,
                              void* d_out, int out_size) {
    const float* x    = (const float*)d_in[0];
    const float* W_ih = (const float*)d_in[1];
    const float* W_hh = (const float*)d_in[2];
    const float* b_ih = (const float*)d_in[3];
    const float* b_hh = (const float*)d_in[4];
    float* out = (float*)d_out;
    const int N = out_size / HDIM;

    lstm_init_kernel<<<1, TPB>>>();
    lstm_kernel<<<NCTA, TPB>>>(x, W_ih, W_hh, b_ih, b_hh, out, N);
}

// round 14
// speedup vs baseline: 1.3231x; 1.3231x over previous
#include <cuda_runtime.h>
#include <cstdint>

// ---------------------------------------------------------------------------
// Sequential LSTM rollout, N=10000 steps, H=1024.
// Wire protocol = R7 exactly (best: 18.6ms): single aggregate counter g_cnt;
//   lane0 of warp0 polls ld.acquire.gpu g_cnt >= 128*t, relays via smem
//   (st.release.cta / ld.acquire.cta spin); publish via __threadfence +
//   red.global.add. ONE __syncthreads per step.
// R13 change: the serial warp-0 tail (reduce+act+c+publish for all 8 outputs)
// is parallelized across warps — warp w owns output cta*8+w:
//   - sh_part padded to stride 33 (conflict-free transposed reads)
//   - 3-level shfl.bfly reduces the 8 warp-partials per gate
//   - 4 gate activations in parallel lane-groups, lane0 updates c, stores h
//   - CTA completion: monotonic atom.acq_rel.cta.shared counter (R10-proven);
//     8th-arriving warp runs the R7-proven fence+red publish tail.
// Safety: counter covers ALL CTAs => 1-step skew bound => parity buffers
// safe; smem atom acq_rel chains all warps' h stores before the fence.
// CTA b owns h[8b..8b+8) and gate rows {g*1024 + 8b + j}.
// Warp w owns k-slice [128w,128w+128) for the FMA and output 8b+w for the tail.
// ---------------------------------------------------------------------------

#define HDIM  1024
#define NCTA  128
#define TPB   256
#define NWARP 8
#define WPT   64           // f32x2 weight pairs per thread (=128 k floats)
#define PSTR  33           // padded sh_part stride (bank-conflict-free)

typedef unsigned long long ull;

__device__ __align__(16) float g_hbuf[2][HDIM];
__device__ unsigned            g_cnt;

__device__ __forceinline__ ull ffma2(ull a, ull b, ull c) {
    ull d;
    asm("fma.rn.f32x2 %0, %1, %2, %3;" : "=l"(d) : "l"(a), "l"(b), "l"(c));
    return d;
}
__device__ __forceinline__ ull fadd2(ull a, ull b) {
    ull d;
    asm("add.rn.f32x2 %0, %1, %2;" : "=l"(d) : "l"(a), "l"(b));
    return d;
}
__device__ __forceinline__ float pairsum(ull a) {
    float lo = __uint_as_float((unsigned)(a & 0xffffffffull));
    float hi = __uint_as_float((unsigned)(a >> 32));
    return lo + hi;
}
__device__ __forceinline__ float sigf(float x) {
    return 1.0f / (1.0f + __expf(-x));
}
__device__ __forceinline__ unsigned ld_acq_gpu(const unsigned* p) {
    unsigned v;
    asm volatile("ld.acquire.gpu.u32 %0, [%1];" : "=r"(v) : "l"(p));
    return v;
}
__device__ __forceinline__ uint32_t smem_u32(const void* p) {
    uint32_t a;
    asm("{ .reg .u64 t; cvta.to.shared.u64 t, %1; cvt.u32.u64 %0, t; }"
        : "=r"(a) : "l"(p));
    return a;
}

__global__ void lstm_init_kernel() {
    if (threadIdx.x == 0) g_cnt = 0u;
}

__global__ void __launch_bounds__(TPB) lstm_kernel(
    const float* __restrict__ x,      // [1024]
    const float* __restrict__ W_ih,   // [4096,1024] row-major
    const float* __restrict__ W_hh,   // [4096,1024] row-major
    const float* __restrict__ b_ih,   // [4096]
    const float* __restrict__ b_hh,   // [4096]
    float* __restrict__ out,          // [N,1024]
    int N)
{
    __shared__ float    sh_h[HDIM];            // warp w owns [128w,128w+128)
    __shared__ float    sh_part[2][NWARP * PSTR]; // parity + padded stride
    __shared__ float    sh_xg[32];             // x-gate values (row gt*H+8b+jj)
    __shared__ unsigned sh_step;               // monotonic step relay
    __shared__ unsigned sh_cnt;                // monotonic warp-completion cnt

    const int tid = threadIdx.x;
    const int w   = tid >> 5;
    const int l   = tid & 31;
    const int cta = blockIdx.x;
    const int gt  = l >> 3;                    // gate 0..3 (i,f,g,o)
    const int jj  = l & 7;                     // local h index 0..7
    const int rowG = gt * HDIM + cta * 8 + jj;
    const int outIdx = cta * 8 + w;            // tail: warp w owns this output
    const uint32_t stepAddr = smem_u32(&sh_step);
    const uint32_t cntAddr  = smem_u32(&sh_cnt);

    if (tid == 0) { sh_step = 0u; sh_cnt = 0u; }

    // ---- stage x into shared (reuse sh_h) ----
    ((float4*)sh_h)[tid] = ((const float4*)x)[tid];
    __syncthreads();

    // ---- prologue: x_gates = x @ W_ih^T + b_ih + b_hh for this CTA's rows ----
    {
        const ull* wp = (const ull*)W_ih + (size_t)rowG * (HDIM / 2) + w * WPT;
        const ull* hp = (const ull*)sh_h + w * WPT;
        ull a0 = 0, a1 = 0, a2 = 0, a3 = 0;
        #pragma unroll
        for (int i = 0; i < WPT; i += 4) {
            a0 = ffma2(wp[i + 0], hp[i + 0], a0);
            a1 = ffma2(wp[i + 1], hp[i + 1], a1);
            a2 = ffma2(wp[i + 2], hp[i + 2], a2);
            a3 = ffma2(wp[i + 3], hp[i + 3], a3);
        }
        a0 = fadd2(a0, a1); a2 = fadd2(a2, a3); a0 = fadd2(a0, a2);
        sh_part[0][w * PSTR + l] = pairsum(a0);
        __syncthreads();
        if (w == 0) {
            float s = 0.f;
            #pragma unroll
            for (int ww = 0; ww < NWARP; ww++) s += sh_part[0][ww * PSTR + l];
            sh_xg[l] = s + b_ih[rowG] + b_hh[rowG];
        }
        __syncthreads();
    }
    // lane l of warp w caches xg(gate l>>3, output w)
    const float xgw = sh_xg[(l >> 3) * 8 + w];
    __syncthreads();     // sh_xg reads done before any reuse; also orders init

    // ---- preload W_hh slice into registers ----
    ull wreg[WPT];
    {
        const ull* wp = (const ull*)W_hh + (size_t)rowG * (HDIM / 2) + w * WPT;
        #pragma unroll
        for (int i = 0; i < WPT; i++) wreg[i] = wp[i];
    }

    // ---- recurrence: ONE __syncthreads per step ----
    float c = 0.f;
    unsigned target = 0u;                      // = 128*t

    for (int t = 0; t < N; ++t) {
        float dot = 0.f;
        if (t > 0) {
            const int p = (t - 1) & 1;
            const unsigned tt = (unsigned)t;

            if (w == 0) {
                if (l == 0) {
                    // single poller per CTA on the aggregate counter
                    while ((int)(ld_acq_gpu(&g_cnt) - target) < 0) { }
                    asm volatile("st.release.cta.shared.u32 [%0], %1;"
                                 :: "r"(stepAddr), "r"(tt) : "memory");
                }
                __syncwarp();
            } else {
                // local smem spin: zero L2 traffic
                unsigned v;
                do {
                    asm volatile("ld.acquire.cta.shared.u32 %0, [%1];"
                                 : "=r"(v) : "r"(stepAddr) : "memory");
                } while ((int)(v - tt) < 0);
            }

            // stage this warp's k-slice into its private smem region
            float4 hv = __ldcg((const float4*)(g_hbuf[p] + w * 128) + l);
            *((float4*)(sh_h + w * 128) + l) = hv;
            __syncwarp();

            const ull* hp = (const ull*)(sh_h + w * 128);
            ull c0 = 0, c1 = 0, c2 = 0, c3 = 0;
            #pragma unroll
            for (int i = 0; i < WPT; i += 4) {
                c0 = ffma2(wreg[i + 0], hp[i + 0], c0);
                c1 = ffma2(wreg[i + 1], hp[i + 1], c1);
                c2 = ffma2(wreg[i + 2], hp[i + 2], c2);
                c3 = ffma2(wreg[i + 3], hp[i + 3], c3);
            }
            c0 = fadd2(c0, c1); c2 = fadd2(c2, c3); c0 = fadd2(c0, c2);
            dot = pairsum(c0);
        }
        sh_part[t & 1][w * PSTR + l] = dot;
        __syncthreads();

        // ---- parallel per-output tail: warp w finishes output cta*8+w ----
        // lane l = (g<<3)|ww reads warp ww's partial for (gate g, output w)
        float v = sh_part[t & 1][(l & 7) * PSTR + (l >> 3) * 8 + w];
        v += __shfl_xor_sync(0xffffffffu, v, 1);
        v += __shfl_xor_sync(0xffffffffu, v, 2);
        v += __shfl_xor_sync(0xffffffffu, v, 4);   // all lanes: gate-g sum
        float val = xgw + v;
        float act = (gt == 2) ? tanhf(val) : sigf(val);
        float a_i = __shfl_sync(0xffffffffu, act, 0);
        float a_f = __shfl_sync(0xffffffffu, act, 8);
        float a_g = __shfl_sync(0xffffffffu, act, 16);
        float a_o = __shfl_sync(0xffffffffu, act, 24);

        if (l == 0) {
            c = a_f * c + a_i * a_g;
            float hn = a_o * tanhf(c);
            __stcg(&g_hbuf[t & 1][outIdx], hn);
            // CTA completion: monotonic acq_rel counter chains all h stores
            unsigned old;
            asm volatile("atom.acq_rel.cta.shared.add.u32 %0, [%1], %2;"
                         : "=r"(old) : "r"(cntAddr), "r"(1u) : "memory");
            if (old == (unsigned)(NWARP * t + (NWARP - 1))) {
                // last warp of this CTA: proven publish tail
                __threadfence();
                asm volatile("red.global.gpu.add.u32 [%0], %1;"
                             :: "l"(&g_cnt), "r"(1u) : "memory");
            }
            // out store after publish: off the critical path
            __stcs(out + (size_t)t * HDIM + outIdx, hn);
        }
        target += NCTA;
        // no trailing barrier: sh_part for step t+1 has opposite parity; the
        // global counter requires ALL CTAs, bounding cross-CTA skew to 1 step.
    }
}

extern "C" void kernel_launch(void* const* d_in, const int* in_sizes, int n_in,
                              void* d_out, int out_size) {
    const float* x    = (const float*)d_in[0];
    const float* W_ih = (const float*)d_in[1];
    const float* W_hh = (const float*)d_in[2];
    const float* b_ih = (const float*)d_in[3];
    const float* b_hh = (const float*)d_in[4];
    float* out = (float*)d_out;
    const int N = out_size / HDIM;

    lstm_init_kernel<<<1, 32>>>();
    lstm_kernel<<<NCTA, TPB>>>(x, W_ih, W_hh, b_ih, b_hh, out, N);
}